// round 2
// baseline (speedup 1.0000x reference)
#include <cuda_runtime.h>
#include <math.h>

#define NWIRES 9
#define NLAYERS 4
#define DDIM 512
#define BATCH 64
#define PPAR 72
#define NGATES 36
#define EMBED 512

typedef unsigned long long u64;

// Scratch (allocation-free: __device__ globals)
__device__ float g_params[BATCH * PPAR];
__device__ float g_coef[BATCH * NGATES * 4];   // c, s, cphi, sphi per gate
__device__ float g_scal[BATCH * 4];            // a1=sin(th)/th, a2=(1-cos th)/th^2, cos th
__device__ float g_Uv[BATCH * DDIM];

// ---- f32x2 helpers (sm_103a packed fp32) ----
__device__ __forceinline__ u64 pk2(float x, float y) {
    u64 d; asm("mov.b64 %0,{%1,%2};" : "=l"(d) : "f"(x), "f"(y)); return d;
}
__device__ __forceinline__ float2 upk2(u64 v) {
    float2 r; asm("mov.b64 {%0,%1},%2;" : "=f"(r.x), "=f"(r.y) : "l"(v)); return r;
}
__device__ __forceinline__ u64 fma2(u64 a, u64 b, u64 c) {
    u64 d; asm("fma.rn.f32x2 %0,%1,%2,%3;" : "=l"(d) : "l"(a), "l"(b), "l"(c)); return d;
}
__device__ __forceinline__ u64 mul2(u64 a, u64 b) {
    u64 d; asm("mul.rn.f32x2 %0,%1,%2;" : "=l"(d) : "l"(a), "l"(b)); return d;
}

// ---------------------------------------------------------------------------
// K1: MLP -> params, gate trig coefficients, rank-2 scalars, zero Uv
// 512 threads: warp w owns e-chunk [32w, 32w+32), lane = output column j.
// w2 reads are coalesced; reduction via smem atomics.
// ---------------------------------------------------------------------------
__global__ __launch_bounds__(512) void k1_params(
        const float* __restrict__ t, const float* __restrict__ w1,
        const float* __restrict__ b1, const float* __restrict__ w2,
        const float* __restrict__ b2) {
    int b = blockIdx.x;
    int tid = threadIdx.x;
    int w = tid >> 5, lane = tid & 31;
    __shared__ float h[EMBED];
    __shared__ float p[PPAR];

    float tv = t[b];
    {
        float x = fmaf(tv, w1[tid], b1[tid]);
        h[tid] = x / (1.f + expf(-x));   // silu
    }
    if (tid < PPAR) p[tid] = 0.f;
    __syncthreads();

    float a0 = 0.f, a1v = 0.f, a2v = 0.f;
    const float* w2base = w2 + (w * 32) * PPAR;
#pragma unroll 8
    for (int k = 0; k < 32; k++) {
        float hv = h[w * 32 + k];
        const float* row = w2base + k * PPAR;
        a0  = fmaf(hv, row[lane], a0);
        a1v = fmaf(hv, row[lane + 32], a1v);
        if (lane < 8) a2v = fmaf(hv, row[lane + 64], a2v);
    }
    atomicAdd(&p[lane], a0);
    atomicAdd(&p[lane + 32], a1v);
    if (lane < 8) atomicAdd(&p[lane + 64], a2v);
    __syncthreads();

    if (tid < PPAR) {
        float v = p[tid] + b2[tid];
        p[tid] = v;
        g_params[b * PPAR + tid] = v;
    }
    g_Uv[b * DDIM + tid] = 0.f;
    __syncthreads();

    if (tid < NGATES) {
        float thy = p[2 * tid], thz = p[2 * tid + 1];
        float* dst = &g_coef[(b * NGATES + tid) * 4];
        dst[0] = cosf(0.5f * thy);
        dst[1] = sinf(0.5f * thy);
        dst[2] = cosf(0.5f * thz);
        dst[3] = sinf(0.5f * thz);
    }
    if (tid == 0) {
        float s2 = 0.f;
        for (int j = 1; j < PPAR; j++) { float vj = 0.01f * p[j]; s2 = fmaf(vj, vj, s2); }
        float th = sqrtf(s2);
        float ct = cosf(th);
        float a1, a2;
        if (th > 1e-6f) { a1 = sinf(th) / th; a2 = (1.f - ct) / s2; }
        else            { a1 = 1.f - s2 * (1.f / 6.f); a2 = 0.5f; }
        g_scal[b * 4 + 0] = a1;
        g_scal[b * 4 + 1] = a2;
        g_scal[b * 4 + 2] = ct;
    }
}

// ---------------------------------------------------------------------------
// K2: circuit simulation, f32x2-packed.
// Amp index n (9 bits): lane = bits[8:4], slot = bits[3:0].
// Slots packed along bit 0: pack r holds slots (2r, 2r+1) as f32x2 {lo,hi}.
// re and im are SEPARATE packs -> both Ry mixing (real coeffs) and Rz phase
// (re<->im cross, uniform per pack) are pure f32x2 FMA. Only wire 8 (slot
// bit 0) is intra-pack; it runs scalar right before the scalar permutation.
// Coefficient sign variants precomputed packed in smem; sign select = LDS offset.
// ---------------------------------------------------------------------------
__global__ __launch_bounds__(512) void k2_sim(float* __restrict__ out) {
    int b    = blockIdx.x >> 5;   // batch
    int grp  = blockIdx.x & 31;   // 32 groups x 16 columns
    int wid  = threadIdx.x >> 5;
    int lane = threadIdx.x & 31;
    int col  = grp * 16 + wid;

    __shared__ u64 gc2[NGATES][6];   // {c,c},{s,s},{-s,-s},{cp,cp},{sp,sp},{-sp,-sp}
    __shared__ float tile[16][513];

    if (threadIdx.x < NGATES) {
        const float* src = &g_coef[(b * NGATES + threadIdx.x) * 4];
        float c = src[0], s = src[1], cp = src[2], sp = src[3];
        gc2[threadIdx.x][0] = pk2(c, c);
        gc2[threadIdx.x][1] = pk2(s, s);
        gc2[threadIdx.x][2] = pk2(-s, -s);
        gc2[threadIdx.x][3] = pk2(cp, cp);
        gc2[threadIdx.x][4] = pk2(sp, sp);
        gc2[threadIdx.x][5] = pk2(-sp, -sp);
    }
    __syncthreads();

    u64 pre[8], pim[8];
#pragma unroll
    for (int r = 0; r < 8; r++) {
        float lo = (((lane << 4) | (2 * r))     == col) ? 1.f : 0.f;
        float hi = (((lane << 4) | (2 * r + 1)) == col) ? 1.f : 0.f;
        pre[r] = pk2(lo, hi);
        pim[r] = 0ull;
    }

    const int par = __popc(lane) & 1;
    const int gl  = lane ^ (lane >> 1);

    float re[16], im[16];

#pragma unroll 1
    for (int L = 0; L < NLAYERS; L++) {
        // --- wires 0..4: lane-bit gates (pbit = 8-w, q = pbit-4 = 4-w) ---
#pragma unroll
        for (int w = 0; w < 5; w++) {
            const u64* g = &gc2[L * NWIRES + w][0];
            const int q = 4 - w;
            int bv = (lane >> q) & 1;
            u64 c2    = g[0];
            u64 ss2   = g[2 - bv];   // bv?{s,s}:{-s,-s}
            u64 cp2   = g[3];
            u64 sps2  = g[5 - bv];   // bv?{sp,sp}:{-sp,-sp}
            u64 nsps2 = g[4 + bv];   // bv?{-sp,-sp}:{sp,sp}
#pragma unroll
            for (int r = 0; r < 8; r++) {
                float2 vr = upk2(pre[r]);
                float2 vi = upk2(pim[r]);
                float oxr = __shfl_xor_sync(0xffffffffu, vr.x, 1 << q);
                float oyr = __shfl_xor_sync(0xffffffffu, vr.y, 1 << q);
                float oxi = __shfl_xor_sync(0xffffffffu, vi.x, 1 << q);
                float oyi = __shfl_xor_sync(0xffffffffu, vi.y, 1 << q);
                u64 ore = pk2(oxr, oyr), oim = pk2(oxi, oyi);
                u64 tre = fma2(c2, pre[r], mul2(ss2, ore));
                u64 tim = fma2(c2, pim[r], mul2(ss2, oim));
                pre[r] = fma2(cp2, tre, mul2(nsps2, tim));
                pim[r] = fma2(cp2, tim, mul2(sps2,  tre));
            }
        }
        // --- wires 5..7: pack-level register gates (pack-bit = 8-w-1) ---
#pragma unroll
        for (int w = 5; w < 8; w++) {
            const u64* g = &gc2[L * NWIRES + w][0];
            const int pb = 8 - w - 1;        // 2,1,0
            const int pm = 1 << pb;
            u64 c2 = g[0], s2 = g[1], ns2 = g[2];
            u64 cp2 = g[3], sp2 = g[4], nsp2 = g[5];
#pragma unroll
            for (int r0 = 0; r0 < 8; r0++) {
                if (r0 & pm) continue;
                const int r1 = r0 | pm;
                u64 t0r = fma2(c2, pre[r0], mul2(ns2, pre[r1]));
                u64 t0i = fma2(c2, pim[r0], mul2(ns2, pim[r1]));
                u64 t1r = fma2(s2, pre[r0], mul2(c2, pre[r1]));
                u64 t1i = fma2(s2, pim[r0], mul2(c2, pim[r1]));
                pre[r0] = fma2(cp2, t0r, mul2(sp2,  t0i));   // e^{-i phi}
                pim[r0] = fma2(cp2, t0i, mul2(nsp2, t0r));
                pre[r1] = fma2(cp2, t1r, mul2(nsp2, t1i));   // e^{+i phi}
                pim[r1] = fma2(cp2, t1i, mul2(sp2,  t1r));
            }
        }
        // --- unpack to scalars for wire 8 + permutation ---
#pragma unroll
        for (int r = 0; r < 8; r++) {
            float2 a = upk2(pre[r]); re[2 * r] = a.x; re[2 * r + 1] = a.y;
            float2 c = upk2(pim[r]); im[2 * r] = c.x; im[2 * r + 1] = c.y;
        }
        // --- wire 8: slot-bit-0 gate, scalar pairs (2k, 2k+1) ---
        {
            const u64* g = &gc2[L * NWIRES + 8][0];
            float c  = upk2(g[0]).x;
            float s  = upk2(g[1]).x;
            float cp = upk2(g[3]).x;
            float sp = upk2(g[4]).x;
#pragma unroll
            for (int k = 0; k < 8; k++) {
                const int r0 = 2 * k, r1 = 2 * k + 1;
                float t0r = fmaf(c, re[r0], -s * re[r1]);
                float t0i = fmaf(c, im[r0], -s * im[r1]);
                float t1r = fmaf(s, re[r0],  c * re[r1]);
                float t1i = fmaf(s, im[r0],  c * im[r1]);
                re[r0] = fmaf(cp, t0r,  sp * t0i);
                im[r0] = fmaf(cp, t0i, -sp * t0r);
                re[r1] = fmaf(cp, t1r, -sp * t1i);
                im[r1] = fmaf(cp, t1i,  sp * t1r);
            }
        }
        // --- composed CNOT-ring permutation (scalar, verified R1) ---
        float nre[16], nim[16];
#pragma unroll
        for (int r = 0; r < 16; r++) {
            const int idx = r ^ (r >> 1);
            int src = (r & 1) ? (gl ^ 24) : gl;
            float prv = par ? re[idx ^ 8] : re[idx];
            float piv = par ? im[idx ^ 8] : im[idx];
            nre[r] = __shfl_sync(0xffffffffu, prv, src);
            nim[r] = __shfl_sync(0xffffffffu, piv, src);
        }
        // --- repack ---
#pragma unroll
        for (int r = 0; r < 8; r++) {
            pre[r] = pk2(nre[2 * r], nre[2 * r + 1]);
            pim[r] = pk2(nim[2 * r], nim[2 * r + 1]);
        }
    }

    // final unpack of real part
#pragma unroll
    for (int r = 0; r < 8; r++) {
        float2 a = upk2(pre[r]); re[2 * r] = a.x; re[2 * r + 1] = a.y;
    }

    // stage real part into smem for coalesced writeback
#pragma unroll
    for (int r = 0; r < 16; r++) tile[wid][(lane << 4) | r] = re[r];

    // Uv[b][i] += Re(U[i,col]) * v[col] for col in 1..71
    if (col >= 1 && col < PPAR) {
        float vc = 0.01f * g_params[b * PPAR + col];
        float* uv = &g_Uv[b * DDIM];
#pragma unroll
        for (int r = 0; r < 16; r++)
            atomicAdd(&uv[(lane << 4) | r], re[r] * vc);
    }

    __syncthreads();

    // coalesced write: out[b][j][grp*16 + c]
    float* obase = out + (size_t)b * DDIM * DDIM + grp * 16;
    int c  = threadIdx.x & 15;
    int j0 = threadIdx.x >> 4;   // 0..31
#pragma unroll
    for (int k = 0; k < 16; k++) {
        int j = k * 32 + j0;
        obase[(size_t)j * DDIM + c] = tile[c][j];
    }
}

// ---------------------------------------------------------------------------
// K3: rank-2 expm update, touches only columns 0..71. One warp per row.
// ---------------------------------------------------------------------------
__global__ void k3_update(float* __restrict__ out) {
    int gw   = (blockIdx.x * blockDim.x + threadIdx.x) >> 5;
    int lane = threadIdx.x & 31;
    int b = gw >> 9;
    int i = gw & 511;
    if (b >= BATCH) return;

    float* row = out + ((size_t)b * DDIM + i) * DDIM;
    float u0  = row[0];
    float uvi = g_Uv[b * DDIM + i];
    float a1 = g_scal[b * 4 + 0];
    float a2 = g_scal[b * 4 + 1];
    float ct = g_scal[b * 4 + 2];
    float f = fmaf(a1, u0, -a2 * uvi);

#pragma unroll
    for (int jj = 0; jj < 3; jj++) {
        int j = lane + jj * 32;
        if (j >= PPAR) break;
        float val;
        if (j == 0) val = fmaf(u0, ct, -a1 * uvi);
        else        val = fmaf(f, 0.01f * g_params[b * PPAR + j], row[j]);
        row[j] = val;
    }
}

// ---------------------------------------------------------------------------
extern "C" void kernel_launch(void* const* d_in, const int* in_sizes, int n_in,
                              void* d_out, int out_size) {
    const float* t  = (const float*)d_in[0];
    const float* w1 = (const float*)d_in[1];
    const float* b1 = (const float*)d_in[2];
    const float* w2 = (const float*)d_in[3];
    const float* b2 = (const float*)d_in[4];
    float* out = (float*)d_out;

    k1_params<<<BATCH, 512>>>(t, w1, b1, w2, b2);
    k2_sim<<<BATCH * 32, 512>>>(out);
    k3_update<<<(BATCH * DDIM) / 8, 256>>>(out);
}

// round 3
// speedup vs baseline: 1.2451x; 1.2451x over previous
#include <cuda_runtime.h>
#include <math.h>

#define NWIRES 9
#define NLAYERS 4
#define DDIM 512
#define BATCH 64
#define PPAR 72
#define NGATES 36
#define EMBED 512

// Scratch (allocation-free: __device__ globals)
__device__ float g_params[BATCH * PPAR];
__device__ float g_coef[BATCH * NGATES * 4];   // c, s, cphi, sphi per gate
__device__ float g_scal[BATCH * 4];            // a1=sin(th)/th, a2=(1-cos th)/th^2, cos th
__device__ float g_Uv[BATCH * DDIM];

// ---------------------------------------------------------------------------
// K1: MLP -> params, gate trig coefficients, rank-2 scalars, zero Uv
// ---------------------------------------------------------------------------
__global__ __launch_bounds__(512) void k1_params(
        const float* __restrict__ t, const float* __restrict__ w1,
        const float* __restrict__ b1, const float* __restrict__ w2,
        const float* __restrict__ b2) {
    int b = blockIdx.x;
    int tid = threadIdx.x;
    int w = tid >> 5, lane = tid & 31;
    __shared__ float h[EMBED];
    __shared__ float p[PPAR];

    float tv = t[b];
    {
        float x = fmaf(tv, w1[tid], b1[tid]);
        h[tid] = x / (1.f + expf(-x));   // silu
    }
    if (tid < PPAR) p[tid] = 0.f;
    __syncthreads();

    float a0 = 0.f, a1v = 0.f, a2v = 0.f;
    const float* w2base = w2 + (w * 32) * PPAR;
#pragma unroll 8
    for (int k = 0; k < 32; k++) {
        float hv = h[w * 32 + k];
        const float* row = w2base + k * PPAR;
        a0  = fmaf(hv, row[lane], a0);
        a1v = fmaf(hv, row[lane + 32], a1v);
        if (lane < 8) a2v = fmaf(hv, row[lane + 64], a2v);
    }
    atomicAdd(&p[lane], a0);
    atomicAdd(&p[lane + 32], a1v);
    if (lane < 8) atomicAdd(&p[lane + 64], a2v);
    __syncthreads();

    if (tid < PPAR) {
        float v = p[tid] + b2[tid];
        p[tid] = v;
        g_params[b * PPAR + tid] = v;
    }
    g_Uv[b * DDIM + tid] = 0.f;
    __syncthreads();

    if (tid < NGATES) {
        float thy = p[2 * tid], thz = p[2 * tid + 1];
        float* dst = &g_coef[(b * NGATES + tid) * 4];
        dst[0] = cosf(0.5f * thy);
        dst[1] = sinf(0.5f * thy);
        dst[2] = cosf(0.5f * thz);
        dst[3] = sinf(0.5f * thz);
    }
    if (tid == 0) {
        float s2 = 0.f;
        for (int j = 1; j < PPAR; j++) { float vj = 0.01f * p[j]; s2 = fmaf(vj, vj, s2); }
        float th = sqrtf(s2);
        float ct = cosf(th);
        float a1, a2;
        if (th > 1e-6f) { a1 = sinf(th) / th; a2 = (1.f - ct) / s2; }
        else            { a1 = 1.f - s2 * (1.f / 6.f); a2 = 0.5f; }
        g_scal[b * 4 + 0] = a1;
        g_scal[b * 4 + 1] = a2;
        g_scal[b * 4 + 2] = ct;
    }
}

// ---------------------------------------------------------------------------
// K2 helpers: real Ry sweep over all 9 wires; the layer's Rz phases are
// factored into one diagonal applied afterwards (exact: gates on distinct
// wires commute, Rz is diagonal).
// Amp index n (9 bits): lane = bits[8:4], slot r = bits[3:0].
// Wire w acts on bit 8-w.
// ---------------------------------------------------------------------------
__device__ __forceinline__ void ry_sweep_full(float* re, float* im,
                                              const float* gf, int L, int lane) {
#pragma unroll
    for (int w = 0; w < 5; w++) {           // lane-bit wires
        float c = gf[(L * 9 + w) * 4 + 0];
        float s = gf[(L * 9 + w) * 4 + 1];
        const int q = 4 - w;
        float ss = ((lane >> q) & 1) ? s : -s;
#pragma unroll
        for (int r = 0; r < 16; r++) {
            float ore = __shfl_xor_sync(0xffffffffu, re[r], 1 << q);
            float oim = __shfl_xor_sync(0xffffffffu, im[r], 1 << q);
            re[r] = fmaf(c, re[r], ss * ore);
            im[r] = fmaf(c, im[r], ss * oim);
        }
    }
#pragma unroll
    for (int w = 5; w < 9; w++) {           // slot-bit wires
        float c = gf[(L * 9 + w) * 4 + 0];
        float s = gf[(L * 9 + w) * 4 + 1];
        const int bit = 1 << (8 - w);
#pragma unroll
        for (int r0 = 0; r0 < 16; r0++) {
            if (r0 & bit) continue;
            const int r1 = r0 | bit;
            float t0r = fmaf(c, re[r0], -s * re[r1]);
            float t1r = fmaf(s, re[r0],  c * re[r1]);
            float t0i = fmaf(c, im[r0], -s * im[r1]);
            float t1i = fmaf(s, im[r0],  c * im[r1]);
            re[r0] = t0r; re[r1] = t1r; im[r0] = t0i; im[r1] = t1i;
        }
    }
}

__device__ __forceinline__ void ry_sweep_re(float* re, const float* gf, int L, int lane) {
#pragma unroll
    for (int w = 0; w < 5; w++) {
        float c = gf[(L * 9 + w) * 4 + 0];
        float s = gf[(L * 9 + w) * 4 + 1];
        const int q = 4 - w;
        float ss = ((lane >> q) & 1) ? s : -s;
#pragma unroll
        for (int r = 0; r < 16; r++) {
            float ore = __shfl_xor_sync(0xffffffffu, re[r], 1 << q);
            re[r] = fmaf(c, re[r], ss * ore);
        }
    }
#pragma unroll
    for (int w = 5; w < 9; w++) {
        float c = gf[(L * 9 + w) * 4 + 0];
        float s = gf[(L * 9 + w) * 4 + 1];
        const int bit = 1 << (8 - w);
#pragma unroll
        for (int r0 = 0; r0 < 16; r0++) {
            if (r0 & bit) continue;
            const int r1 = r0 | bit;
            float t0r = fmaf(c, re[r0], -s * re[r1]);
            float t1r = fmaf(s, re[r0],  c * re[r1]);
            re[r0] = t0r; re[r1] = t1r;
        }
    }
}

// composed CNOT-ring permutation (verified R1): new[l,r] = old[src, idx(^8)]
__device__ __forceinline__ void perm_full(float* re, float* im, int lane, int par, int gl) {
    float nre[16], nim[16];
#pragma unroll
    for (int r = 0; r < 16; r++) {
        const int idx = r ^ (r >> 1);
        int src = (r & 1) ? (gl ^ 24) : gl;
        float prv = par ? re[idx ^ 8] : re[idx];
        float piv = par ? im[idx ^ 8] : im[idx];
        nre[r] = __shfl_sync(0xffffffffu, prv, src);
        nim[r] = __shfl_sync(0xffffffffu, piv, src);
    }
#pragma unroll
    for (int r = 0; r < 16; r++) { re[r] = nre[r]; im[r] = nim[r]; }
}

__device__ __forceinline__ void perm_re(float* re, int lane, int par, int gl) {
    float nre[16];
#pragma unroll
    for (int r = 0; r < 16; r++) {
        const int idx = r ^ (r >> 1);
        int src = (r & 1) ? (gl ^ 24) : gl;
        float prv = par ? re[idx ^ 8] : re[idx];
        nre[r] = __shfl_sync(0xffffffffu, prv, src);
    }
#pragma unroll
    for (int r = 0; r < 16; r++) re[r] = nre[r];
}

// ---------------------------------------------------------------------------
// K2: circuit simulation. One column per warp; real Ry sweeps + per-layer
// diagonal phase table (precomputed in prologue, smem).
// ---------------------------------------------------------------------------
__global__ __launch_bounds__(512) void k2_sim(float* __restrict__ out) {
    int b    = blockIdx.x >> 5;   // batch
    int grp  = blockIdx.x & 31;   // 32 groups x 16 columns
    int wid  = threadIdx.x >> 5;
    int lane = threadIdx.x & 31;
    int col  = grp * 16 + wid;
    int tid  = threadIdx.x;

    __shared__ float gf[NGATES * 4];
    // union: phase tables (16 KB) during the layer loop, writeback tile after
    __shared__ __align__(16) char ubuf[16 * 513 * 4];
    float2 (*ph)[16][32] = reinterpret_cast<float2 (*)[16][32]>(ubuf); // [L][r][lane]
    float  (*tile)[513]  = reinterpret_cast<float (*)[513]>(ubuf);

    if (tid < NGATES * 4) gf[tid] = g_coef[b * NGATES * 4 + tid];
    __syncthreads();

    // prologue: per-layer diagonal phase(n) = prod_w (cp_w, +/- sp_w), n = tid
    {
        const int n = tid;
#pragma unroll
        for (int L = 0; L < NLAYERS; L++) {
            float pr = 1.f, pi = 0.f;
#pragma unroll
            for (int w = 0; w < 9; w++) {
                float cp = gf[(L * 9 + w) * 4 + 2];
                float sp = gf[(L * 9 + w) * 4 + 3];
                float sg = ((n >> (8 - w)) & 1) ? sp : -sp;
                float nr = fmaf(pr, cp, -pi * sg);
                float ni = fmaf(pr, sg,  pi * cp);
                pr = nr; pi = ni;
            }
            ph[L][n & 15][n >> 4] = make_float2(pr, pi);
        }
    }
    __syncthreads();

    float re[16], im[16];
#pragma unroll
    for (int r = 0; r < 16; r++)
        re[r] = (((lane << 4) | r) == col) ? 1.f : 0.f;

    const int par = __popc(lane) & 1;
    const int gl  = lane ^ (lane >> 1);

    // ---- layer 0: state real through Ry; phase creates im ----
    ry_sweep_re(re, gf, 0, lane);
#pragma unroll
    for (int r = 0; r < 16; r++) {
        float2 p = ph[0][r][lane];
        im[r] = p.y * re[r];
        re[r] = p.x * re[r];
    }
    perm_full(re, im, lane, par, gl);

    // ---- layers 1,2: full complex ----
#pragma unroll 1
    for (int L = 1; L <= 2; L++) {
        ry_sweep_full(re, im, gf, L, lane);
#pragma unroll
        for (int r = 0; r < 16; r++) {
            float2 p = ph[L][r][lane];
            float tr = fmaf(p.x, re[r], -p.y * im[r]);
            float ti = fmaf(p.y, re[r],  p.x * im[r]);
            re[r] = tr; im[r] = ti;
        }
        perm_full(re, im, lane, par, gl);
    }

    // ---- layer 3: only Re needed downstream ----
    ry_sweep_full(re, im, gf, 3, lane);
#pragma unroll
    for (int r = 0; r < 16; r++) {
        float2 p = ph[3][r][lane];
        re[r] = fmaf(p.x, re[r], -p.y * im[r]);
    }
    perm_re(re, lane, par, gl);

    // Uv[b][i] += Re(U[i,col]) * v[col] for col in 1..71
    if (col >= 1 && col < PPAR) {
        float vc = 0.01f * g_params[b * PPAR + col];
        float* uv = &g_Uv[b * DDIM];
#pragma unroll
        for (int r = 0; r < 16; r++)
            atomicAdd(&uv[(lane << 4) | r], re[r] * vc);
    }

    __syncthreads();   // phase tables dead; reuse ubuf as tile

#pragma unroll
    for (int r = 0; r < 16; r++) tile[wid][(lane << 4) | r] = re[r];
    __syncthreads();

    // coalesced write: out[b][j][grp*16 + c]
    float* obase = out + (size_t)b * DDIM * DDIM + grp * 16;
    int c  = tid & 15;
    int j0 = tid >> 4;   // 0..31
#pragma unroll
    for (int k = 0; k < 16; k++) {
        int j = k * 32 + j0;
        obase[(size_t)j * DDIM + c] = tile[c][j];
    }
}

// ---------------------------------------------------------------------------
// K3: rank-2 expm update, touches only columns 0..71. One warp per row.
// ---------------------------------------------------------------------------
__global__ void k3_update(float* __restrict__ out) {
    int gw   = (blockIdx.x * blockDim.x + threadIdx.x) >> 5;
    int lane = threadIdx.x & 31;
    int b = gw >> 9;
    int i = gw & 511;
    if (b >= BATCH) return;

    float* row = out + ((size_t)b * DDIM + i) * DDIM;
    float u0  = row[0];
    float uvi = g_Uv[b * DDIM + i];
    float a1 = g_scal[b * 4 + 0];
    float a2 = g_scal[b * 4 + 1];
    float ct = g_scal[b * 4 + 2];
    float f = fmaf(a1, u0, -a2 * uvi);

#pragma unroll
    for (int jj = 0; jj < 3; jj++) {
        int j = lane + jj * 32;
        if (j >= PPAR) break;
        float val;
        if (j == 0) val = fmaf(u0, ct, -a1 * uvi);
        else        val = fmaf(f, 0.01f * g_params[b * PPAR + j], row[j]);
        row[j] = val;
    }
}

// ---------------------------------------------------------------------------
extern "C" void kernel_launch(void* const* d_in, const int* in_sizes, int n_in,
                              void* d_out, int out_size) {
    const float* t  = (const float*)d_in[0];
    const float* w1 = (const float*)d_in[1];
    const float* b1 = (const float*)d_in[2];
    const float* w2 = (const float*)d_in[3];
    const float* b2 = (const float*)d_in[4];
    float* out = (float*)d_out;

    k1_params<<<BATCH, 512>>>(t, w1, b1, w2, b2);
    k2_sim<<<BATCH * 32, 512>>>(out);
    k3_update<<<(BATCH * DDIM) / 8, 256>>>(out);
}